// round 11
// baseline (speedup 1.0000x reference)
#include <cuda_runtime.h>
#include <cuda_bf16.h>
#include <math.h>

#define SEQ 512
#define BB  64
#define EMB 512
#define HID 1024
#define NG  4096
#define NM  32768

typedef unsigned long long ull;

// ---------------- device scratch ----------------
__device__ float d_gx[(size_t)SEQ * NG * BB];                  // [s][R][b]
__device__ __align__(16) __nv_bfloat16 d_wxb[(size_t)2 * NG * EMB];
__device__ float d_bxr[NG];
__device__ __align__(16) __nv_bfloat16 d_whb[(size_t)2 * NG * HID];
__device__ __align__(16) __nv_bfloat16 d_ebf[(size_t)2 * NM * EMB];
__device__ __align__(16) __nv_bfloat16 d_hbf[2][BB * HID];
__device__ float d_hfin[BB * HID];
__device__ float d_cst[BB * HID];
__device__ int   d_bar;

// ---------------- helpers ----------------
__device__ __forceinline__ float sigf(float x) { return 1.0f / (1.0f + __expf(-x)); }

__device__ __forceinline__ void cp16(void* smem_dst, const void* gsrc) {
    unsigned d = (unsigned)__cvta_generic_to_shared(smem_dst);
    asm volatile("cp.async.cg.shared.global [%0], [%1], 16;" :: "r"(d), "l"(gsrc));
}
__device__ __forceinline__ void cp_commit() { asm volatile("cp.async.commit_group;"); }
template <int N> __device__ __forceinline__ void cp_wait() {
    asm volatile("cp.async.wait_group %0;" :: "n"(N));
}
__device__ __forceinline__ unsigned smem_u32(const void* p) {
    return (unsigned)__cvta_generic_to_shared(p);
}
__device__ __forceinline__ void ldm_x4(unsigned& r0, unsigned& r1, unsigned& r2, unsigned& r3,
                                       unsigned addr) {
    asm volatile("ldmatrix.sync.aligned.m8n8.x4.shared.b16 {%0,%1,%2,%3}, [%4];"
                 : "=r"(r0), "=r"(r1), "=r"(r2), "=r"(r3) : "r"(addr));
}
__device__ __forceinline__ void ldm_x2(unsigned& r0, unsigned& r1, unsigned addr) {
    asm volatile("ldmatrix.sync.aligned.m8n8.x2.shared.b16 {%0,%1}, [%2];"
                 : "=r"(r0), "=r"(r1) : "r"(addr));
}
__device__ __forceinline__ void mma16816(float* d, const unsigned* a, unsigned b0, unsigned b1) {
    asm volatile(
        "mma.sync.aligned.m16n8k16.row.col.f32.bf16.bf16.f32 "
        "{%0,%1,%2,%3}, {%4,%5,%6,%7}, {%8,%9}, {%0,%1,%2,%3};"
        : "+f"(d[0]), "+f"(d[1]), "+f"(d[2]), "+f"(d[3])
        : "r"(a[0]), "r"(a[1]), "r"(a[2]), "r"(a[3]), "r"(b0), "r"(b1));
}
__device__ __forceinline__ ull pack4bf(float a, float b, float c, float d,
                                       float& la, float& lb, float& lc, float& ld) {
    __nv_bfloat16 h0 = __float2bfloat16_rn(a), h1 = __float2bfloat16_rn(b);
    __nv_bfloat16 h2 = __float2bfloat16_rn(c), h3 = __float2bfloat16_rn(d);
    la = a - __bfloat162float(h0); lb = b - __bfloat162float(h1);
    lc = c - __bfloat162float(h2); ld = d - __bfloat162float(h3);
    ull r = (ull)*(unsigned short*)&h0 | ((ull)*(unsigned short*)&h1 << 16)
          | ((ull)*(unsigned short*)&h2 << 32) | ((ull)*(unsigned short*)&h3 << 48);
    return r;
}

// =====================================================================
// prepack (unchanged)
// =====================================================================
__global__ void prepack_kernel(
    const float* __restrict__ W_ii, const float* __restrict__ b_ii, const float* __restrict__ W_hi,
    const float* __restrict__ W_if, const float* __restrict__ b_if, const float* __restrict__ W_hf,
    const float* __restrict__ W_ig, const float* __restrict__ b_ig, const float* __restrict__ W_hg,
    const float* __restrict__ W_io, const float* __restrict__ b_io, const float* __restrict__ W_ho)
{
    const size_t stride = (size_t)gridDim.x * blockDim.x;
    const size_t tid = (size_t)blockIdx.x * blockDim.x + threadIdx.x;

    if (tid == 0) d_bar = 0;

    for (size_t i = tid; i < (size_t)NG * EMB; i += stride) {
        int R = (int)(i >> 9), k = (int)(i & 511);
        int cta = R >> 5, g = (R >> 3) & 3, jj = R & 7;
        int j = cta * 8 + jj;
        const float* w = (g == 0) ? W_ii : (g == 1) ? W_if : (g == 2) ? W_ig : W_io;
        float v = w[j * EMB + k];
        __nv_bfloat16 hi = __float2bfloat16_rn(v);
        d_wxb[i] = hi;
        d_wxb[(size_t)NG * EMB + i] = __float2bfloat16_rn(v - __bfloat162float(hi));
    }
    for (size_t i = tid; i < NG; i += stride) {
        int R = (int)i;
        int cta = R >> 5, g = (R >> 3) & 3, jj = R & 7;
        int j = cta * 8 + jj;
        const float* b = (g == 0) ? b_ii : (g == 1) ? b_if : (g == 2) ? b_ig : b_io;
        d_bxr[R] = b[j];
    }
    for (size_t i = tid; i < (size_t)2 * NG * HID; i += stride) {
        int Re = (int)(i >> 10), k = (int)(i & 1023);
        int cta = Re >> 6, rem = Re & 63;
        int split = rem >> 5, local = rem & 31;
        int g = local >> 3, jj = local & 7;
        int j = cta * 8 + jj;
        const float* w = (g == 0) ? W_hi : (g == 1) ? W_hf : (g == 2) ? W_hg : W_ho;
        float v = w[j * HID + k];
        __nv_bfloat16 hi = __float2bfloat16_rn(v);
        if (split == 0) d_whb[i] = hi;
        else            d_whb[i] = __float2bfloat16_rn(v - __bfloat162float(hi));
    }
    for (size_t i = tid; i < BB * HID; i += stride) {
        d_hbf[0][i] = __float2bfloat16_rn(0.0f);
        d_hbf[1][i] = __float2bfloat16_rn(0.0f);
    }
}

// =====================================================================
// gather (unchanged)
// =====================================================================
__global__ void gather_kernel(const int* __restrict__ x, const float* __restrict__ emb)
{
    ull* ehi = (ull*)d_ebf;
    ull* elo = (ull*)(d_ebf + (size_t)NM * EMB);
    const size_t stride = (size_t)gridDim.x * blockDim.x;
    for (size_t idx = (size_t)blockIdx.x * blockDim.x + threadIdx.x;
         idx < (size_t)NM * 128; idx += stride) {
        int m = (int)(idx >> 7), q = (int)(idx & 127);
        int s = m >> 6, b = m & 63;
        int tok = __ldg(&x[b * SEQ + s]);
        float4 v = *(const float4*)(emb + (size_t)tok * EMB + q * 4);
        float la, lb, lc, ld;
        ull hv = pack4bf(v.x, v.y, v.z, v.w, la, lb, lc, ld);
        float dum0, dum1, dum2, dum3;
        ull lv = pack4bf(la, lb, lc, ld, dum0, dum1, dum2, dum3);
        ehi[(size_t)m * 128 + q] = hv;
        elo[(size_t)m * 128 + q] = lv;
    }
}

// =====================================================================
// gx2 (unchanged from passing round)
// =====================================================================
#define G2_PITCH 144
#define G2_SPL   18432
#define G2_BUFSZ 36864
#define G2_OFF_B 73728
#define G2_SMEM  147456

__global__ void __launch_bounds__(256, 1) gx2_kernel()
{
    extern __shared__ char smc[];
    const unsigned smb = smem_u32(smc);
    const int t = threadIdx.x, w = t >> 5, lane = t & 31;
    const int mty = blockIdx.x;
    const int ntx = blockIdx.y;
    const int wm = w >> 1, wn = w & 1;
    const int lrow = lane & 15;
    const int kh2 = (lane >> 4) * 16;

    const __nv_bfloat16* wsrc = d_wxb;
    const __nv_bfloat16* esrc = d_ebf;

    float d[2][4][2][4];
#pragma unroll
    for (int mt = 0; mt < 2; mt++)
#pragma unroll
        for (int bt = 0; bt < 4; bt++)
#pragma unroll
            for (int hf = 0; hf < 2; hf++)
#pragma unroll
                for (int q = 0; q < 4; q++) d[mt][bt][hf][q] = 0.0f;

    auto stage = [&](int cb) {
        const int buf = cb & 1;
        char* abase = smc + buf * G2_BUFSZ;
        char* bbase = smc + G2_OFF_B + buf * G2_BUFSZ;
#pragma unroll
        for (int i = 0; i < 8; i++) {
            int u = t + i * 256;
            int split = u >> 10, r = (u >> 3) & 127, q = u & 7;
            cp16(abase + split * G2_SPL + r * G2_PITCH + q * 16,
                 wsrc + (size_t)split * NG * EMB + (size_t)(mty * 128 + r) * EMB + cb * 64 + q * 8);
        }
#pragma unroll
        for (int i = 0; i < 8; i++) {
            int u = t + i * 256;
            int split = u >> 10, r = (u >> 3) & 127, q = u & 7;
            cp16(bbase + split * G2_SPL + r * G2_PITCH + q * 16,
                 esrc + (size_t)split * NM * EMB + (size_t)(ntx * 128 + r) * EMB + cb * 64 + q * 8);
        }
        cp_commit();
    };

    stage(0);

    for (int cb = 0; cb < 8; cb++) {
        if (cb < 7) { stage(cb + 1); cp_wait<1>(); }
        else        { cp_wait<0>(); }
        __syncthreads();

        const unsigned abase = smb + (cb & 1) * G2_BUFSZ;
        const unsigned bbase = smb + G2_OFF_B + (cb & 1) * G2_BUFSZ;
#pragma unroll
        for (int k16 = 0; k16 < 4; k16++) {
            const int kB = k16 * 32 + kh2;
            unsigned Ah[2][4], Al[2][4];
#pragma unroll
            for (int mt = 0; mt < 2; mt++) {
                unsigned ar = abase + (wm * 32 + mt * 16 + lrow) * G2_PITCH + kB;
                ldm_x4(Ah[mt][0], Ah[mt][1], Ah[mt][2], Ah[mt][3], ar);
                ldm_x4(Al[mt][0], Al[mt][1], Al[mt][2], Al[mt][3], ar + G2_SPL);
            }
#pragma unroll
            for (int bt = 0; bt < 4; bt++) {
                unsigned br = bbase + (wn * 64 + bt * 16 + lrow) * G2_PITCH + kB;
                unsigned bh0, bh1, bh2, bh3, bl0, bl1, bl2, bl3;
                ldm_x4(bh0, bh1, bh2, bh3, br);
                ldm_x4(bl0, bl1, bl2, bl3, br + G2_SPL);
#pragma unroll
                for (int mt = 0; mt < 2; mt++) {
                    mma16816(d[mt][bt][0], Ah[mt], bh0, bh2);
                    mma16816(d[mt][bt][1], Ah[mt], bh1, bh3);
                    mma16816(d[mt][bt][0], Al[mt], bh0, bh2);
                    mma16816(d[mt][bt][1], Al[mt], bh1, bh3);
                    mma16816(d[mt][bt][0], Ah[mt], bl0, bl2);
                    mma16816(d[mt][bt][1], Ah[mt], bl1, bl3);
                }
            }
        }
        __syncthreads();
    }

#pragma unroll
    for (int mt = 0; mt < 2; mt++) {
        int Rg0 = mty * 128 + wm * 32 + mt * 16 + (lane >> 2);
        int Rg1 = Rg0 + 8;
        float bi0 = __ldg(&d_bxr[Rg0]);
        float bi1 = __ldg(&d_bxr[Rg1]);
#pragma unroll
        for (int bt = 0; bt < 4; bt++)
#pragma unroll
            for (int hf = 0; hf < 2; hf++) {
                int col = wn * 64 + bt * 16 + hf * 8 + 2 * (lane & 3);
                int m = ntx * 128 + col;
                int s = m >> 6, b = m & 63;
                float* q = d[mt][bt][hf];
                *(float2*)(&d_gx[((size_t)s * NG + Rg0) * BB + b]) =
                    make_float2(q[0] + bi0, q[1] + bi0);
                *(float2*)(&d_gx[((size_t)s * NG + Rg1) * BB + b]) =
                    make_float2(q[2] + bi1, q[3] + bi1);
            }
    }
}

// =====================================================================
// persistent mma.sync step kernel — 512 threads / 16 warps.
// Warp tile 16m x 8n: wn = w&7, wm = w>>3. Per k16: ldm.x4 A hi/lo,
// ldm.x2 B hi/lo, 3 mma into one accumulator. gx(s+1) prefetched inside
// the barrier window.
// =====================================================================
#define W_PITCH 2064
#define H_PITCH 272
#define HBUF (64 * H_PITCH)
#define OFF_W   0
#define OFF_H   132096
#define OFF_SG  201728
#define OFF_SGX 210432
#define TC_SMEM 219136

__global__ void __launch_bounds__(512, 1) persist_mma_kernel()
{
    extern __shared__ char smc[];
    float* sg  = (float*)(smc + OFF_SG);
    float* sgx = (float*)(smc + OFF_SGX);

    const int t = threadIdx.x, w = t >> 5, lane = t & 31;
    const int cta = blockIdx.x;
    const int wn = w & 7, wm = w >> 3;
    const unsigned smb = smem_u32(smc);

    // ---- stage W slab once: 64 ext rows x 2048 B ----
    const char* wsrc = (const char*)(d_whb + (size_t)cta * 64 * HID);
#pragma unroll
    for (int i = 0; i < 16; i++) {
        int u = t + i * 512;
        int r = u >> 7, q = u & 127;
        cp16(smc + OFF_W + r * W_PITCH + q * 16, wsrc + r * 2048 + q * 16);
    }
    cp_commit();

    // A-fragment lane map
    const int lrow = lane & 15;
    const int kh2 = (lane >> 4) * 16;
    // B-fragment (x2) lane map
    const int l8 = lane & 7;
    const int bsel = (lane >> 3) & 1;

    // pointwise map: one (j, b) cell per thread
    const int be = t & 63, jj = t >> 6;
    const int jglob = cta * 8 + jj;
    float creg = 0.0f;

    // prefetch gx for s = 0
    {
        int r = t >> 4, bq = (t & 15) * 4;
        cp16((char*)sgx + (r * 68 + bq) * 4,
             d_gx + ((size_t)0 * NG + cta * 32 + r) * BB + bq);
        cp_commit();
    }
    cp_wait<0>();   // W + gx0 ready
    __syncthreads();

    for (int s = 0; s < SEQ; s++) {
        // ---- stage h chunk 0 ----
#pragma unroll
        for (int i = 0; i < 4; i++) {
            int u = t + i * 512;
            int split = u >> 10, r = (u >> 4) & 63, q = u & 15;
            cp16(smc + OFF_H + split * HBUF + r * H_PITCH + q * 16,
                 (const char*)d_hbf[split] + r * 2048 + 0 + q * 16);
        }
        cp_commit();

        float d[4] = {0.0f, 0.0f, 0.0f, 0.0f};

        for (int kb = 0; kb < 8; kb++) {
            __syncthreads();   // all warps done with buf (kb+1)&1
            if (kb < 7) {
                char* nxt = smc + OFF_H + ((kb + 1) & 1) * 2 * HBUF;
#pragma unroll
                for (int i = 0; i < 4; i++) {
                    int u = t + i * 512;
                    int split = u >> 10, r = (u >> 4) & 63, q = u & 15;
                    cp16(nxt + split * HBUF + r * H_PITCH + q * 16,
                         (const char*)d_hbf[split] + r * 2048 + (kb + 1) * 256 + q * 16);
                }
                cp_commit();
                cp_wait<1>();
            } else {
                cp_wait<0>();
            }
            __syncthreads();   // chunk kb visible

            const unsigned aw  = smb + OFF_W + (wm * 16 + lrow) * W_PITCH + kb * 256;
            const unsigned awl = aw + 32 * W_PITCH;
            const unsigned hb  = smb + OFF_H + (kb & 1) * 2 * HBUF
                               + (wn * 8 + l8) * H_PITCH + bsel * 16;
#pragma unroll
            for (int k16 = 0; k16 < 8; k16++) {
                const int kA = k16 * 32 + kh2;
                const int kB = k16 * 32;
                unsigned ah[4], al[4];
                unsigned bh0, bh1, bl0, bl1;
                ldm_x4(ah[0], ah[1], ah[2], ah[3], aw + kA);
                ldm_x4(al[0], al[1], al[2], al[3], awl + kA);
                ldm_x2(bh0, bh1, hb + kB);
                ldm_x2(bl0, bl1, hb + HBUF + kB);
                mma16816(d, ah, bh0, bh1);
                mma16816(d, al, bh0, bh1);
                mma16816(d, ah, bl0, bl1);
            }
        }
        __syncthreads();

        // ---- write D tile into sg[row][b] ----
        {
            int row = wm * 16 + (lane >> 2);
            int col = wn * 8 + (lane & 3) * 2;
            sg[row * 68 + col]           = d[0];
            sg[row * 68 + col + 1]       = d[1];
            sg[(row + 8) * 68 + col]     = d[2];
            sg[(row + 8) * 68 + col + 1] = d[3];
        }
        __syncthreads();

        // ---- pointwise ----
        float g[4];
#pragma unroll
        for (int gg = 0; gg < 4; gg++) {
            int r = gg * 8 + jj;
            g[gg] = sg[r * 68 + be] + sgx[r * 68 + be];
        }
        float it_ = sigf(g[0]);
        float ft  = sigf(g[1]);
        float gt  = tanhf(g[2]);
        float ot  = sigf(g[3]);
        float c = ft * creg + it_ * gt;
        creg = c;
        float h = ot * tanhf(c);
        __nv_bfloat16 hh = __float2bfloat16_rn(h);
        __nv_bfloat16 hl = __float2bfloat16_rn(h - __bfloat162float(hh));
        *(unsigned short*)(&d_hbf[0][be * HID + jglob]) = *(unsigned short*)&hh;
        *(unsigned short*)(&d_hbf[1][be * HID + jglob]) = *(unsigned short*)&hl;
        if (s == SEQ - 1)
            d_hfin[be * HID + jglob] = h;

        // ---- barrier: arrive, prefetch gx(s+1) in the wait window, poll ----
        __threadfence();
        __syncthreads();
        if (t == 0) atomicAdd(&d_bar, 1);
        if (s + 1 < SEQ) {
            int r = t >> 4, bq = (t & 15) * 4;
            cp16((char*)sgx + (r * 68 + bq) * 4,
                 d_gx + ((size_t)(s + 1) * NG + cta * 32 + r) * BB + bq);
            cp_commit();
        }
        if (t == 0) {
            const int target = 128 * (s + 1);
            while (*(volatile int*)&d_bar < target) { }
        }
        __syncthreads();
    }

    d_cst[be * HID + jglob] = creg;
}

// =====================================================================
// head
// =====================================================================
__global__ void head_kernel(const float* __restrict__ Vw, const float* __restrict__ Vb,
                            float* __restrict__ out)
{
    const int b = blockIdx.x, t = threadIdx.x;
    float s0 = 0.0f, s1 = 0.0f;
    for (int k = t; k < HID; k += 256) {
        float hv = d_hfin[b * HID + k];
        s0 += hv * Vw[k];
        s1 += hv * Vw[HID + k];
        out[128 + b * HID + k] = hv;
        out[128 + BB * HID + b * HID + k] = d_cst[b * HID + k];
    }
    __shared__ float r0[256], r1[256];
    r0[t] = s0; r1[t] = s1;
    __syncthreads();
    for (int off = 128; off > 0; off >>= 1) {
        if (t < off) { r0[t] += r0[t + off]; r1[t] += r1[t + off]; }
        __syncthreads();
    }
    if (t == 0) {
        out[b * 2 + 0] = r0[0] + Vb[0];
        out[b * 2 + 1] = r1[0] + Vb[1];
    }
}

// =====================================================================
extern "C" void kernel_launch(void* const* d_in, const int* in_sizes, int n_in,
                              void* d_out, int out_size)
{
    (void)in_sizes; (void)n_in; (void)out_size;
    const int*   x   = (const int*)d_in[0];
    const float* emb = (const float*)d_in[1];

    cudaFuncSetAttribute(gx2_kernel,         cudaFuncAttributeMaxDynamicSharedMemorySize, G2_SMEM);
    cudaFuncSetAttribute(persist_mma_kernel, cudaFuncAttributeMaxDynamicSharedMemorySize, TC_SMEM);

    prepack_kernel<<<1024, 256>>>(
        (const float*)d_in[2],  (const float*)d_in[3],  (const float*)d_in[4],
        (const float*)d_in[5],  (const float*)d_in[6],  (const float*)d_in[7],
        (const float*)d_in[8],  (const float*)d_in[9],  (const float*)d_in[10],
        (const float*)d_in[11], (const float*)d_in[12], (const float*)d_in[13]);

    gather_kernel<<<2048, 256>>>(x, emb);

    gx2_kernel<<<dim3(32, 256), 256, G2_SMEM>>>();

    persist_mma_kernel<<<128, 512, TC_SMEM>>>();

    head_kernel<<<BB, 256>>>((const float*)d_in[14], (const float*)d_in[15], (float*)d_out);
}

// round 12
// speedup vs baseline: 1.5009x; 1.5009x over previous
#include <cuda_runtime.h>
#include <cuda_bf16.h>
#include <cuda_fp16.h>
#include <math.h>

#define SEQ 512
#define BB  64
#define EMB 512
#define HID 1024
#define NG  4096
#define NM  32768

typedef unsigned long long ull;

// ---------------- device scratch ----------------
__device__ float d_gx[(size_t)SEQ * NG * BB];                  // [s][R][b]
__device__ __align__(16) __nv_bfloat16 d_wxb[(size_t)2 * NG * EMB];
__device__ float d_bxr[NG];
__device__ __align__(16) __half d_whf[(size_t)2 * NG * HID];   // Wh fp16 hi/lo, cta-slab order
__device__ __align__(16) __nv_bfloat16 d_ebf[(size_t)2 * NM * EMB];
__device__ __align__(16) __half d_hf16[2][BB * HID];           // h fp16, ping-pong
__device__ float d_hfin[BB * HID];
__device__ float d_cst[BB * HID];
__device__ int   d_bar;

// ---------------- helpers ----------------
__device__ __forceinline__ float sigf(float x) { return 1.0f / (1.0f + __expf(-x)); }

__device__ __forceinline__ void cp16(void* smem_dst, const void* gsrc) {
    unsigned d = (unsigned)__cvta_generic_to_shared(smem_dst);
    asm volatile("cp.async.cg.shared.global [%0], [%1], 16;" :: "r"(d), "l"(gsrc));
}
__device__ __forceinline__ void cp_commit() { asm volatile("cp.async.commit_group;"); }
template <int N> __device__ __forceinline__ void cp_wait() {
    asm volatile("cp.async.wait_group %0;" :: "n"(N));
}
__device__ __forceinline__ unsigned smem_u32(const void* p) {
    return (unsigned)__cvta_generic_to_shared(p);
}
__device__ __forceinline__ void ldm_x4(unsigned& r0, unsigned& r1, unsigned& r2, unsigned& r3,
                                       unsigned addr) {
    asm volatile("ldmatrix.sync.aligned.m8n8.x4.shared.b16 {%0,%1,%2,%3}, [%4];"
                 : "=r"(r0), "=r"(r1), "=r"(r2), "=r"(r3) : "r"(addr));
}
__device__ __forceinline__ void mma16816bf(float* d, const unsigned* a, unsigned b0, unsigned b1) {
    asm volatile(
        "mma.sync.aligned.m16n8k16.row.col.f32.bf16.bf16.f32 "
        "{%0,%1,%2,%3}, {%4,%5,%6,%7}, {%8,%9}, {%0,%1,%2,%3};"
        : "+f"(d[0]), "+f"(d[1]), "+f"(d[2]), "+f"(d[3])
        : "r"(a[0]), "r"(a[1]), "r"(a[2]), "r"(a[3]), "r"(b0), "r"(b1));
}
__device__ __forceinline__ void mma16816f16(float* d, const unsigned* a, unsigned b0, unsigned b1) {
    asm volatile(
        "mma.sync.aligned.m16n8k16.row.col.f32.f16.f16.f32 "
        "{%0,%1,%2,%3}, {%4,%5,%6,%7}, {%8,%9}, {%0,%1,%2,%3};"
        : "+f"(d[0]), "+f"(d[1]), "+f"(d[2]), "+f"(d[3])
        : "r"(a[0]), "r"(a[1]), "r"(a[2]), "r"(a[3]), "r"(b0), "r"(b1));
}
__device__ __forceinline__ ull pack4bf(float a, float b, float c, float d,
                                       float& la, float& lb, float& lc, float& ld) {
    __nv_bfloat16 h0 = __float2bfloat16_rn(a), h1 = __float2bfloat16_rn(b);
    __nv_bfloat16 h2 = __float2bfloat16_rn(c), h3 = __float2bfloat16_rn(d);
    la = a - __bfloat162float(h0); lb = b - __bfloat162float(h1);
    lc = c - __bfloat162float(h2); ld = d - __bfloat162float(h3);
    ull r = (ull)*(unsigned short*)&h0 | ((ull)*(unsigned short*)&h1 << 16)
          | ((ull)*(unsigned short*)&h2 << 32) | ((ull)*(unsigned short*)&h3 << 48);
    return r;
}

// =====================================================================
// prepack: Wx bf16 hi/lo R-order; Wh fp16 hi/lo cta-slab order; zero h.
// =====================================================================
__global__ void prepack_kernel(
    const float* __restrict__ W_ii, const float* __restrict__ b_ii, const float* __restrict__ W_hi,
    const float* __restrict__ W_if, const float* __restrict__ b_if, const float* __restrict__ W_hf,
    const float* __restrict__ W_ig, const float* __restrict__ b_ig, const float* __restrict__ W_hg,
    const float* __restrict__ W_io, const float* __restrict__ b_io, const float* __restrict__ W_ho)
{
    const size_t stride = (size_t)gridDim.x * blockDim.x;
    const size_t tid = (size_t)blockIdx.x * blockDim.x + threadIdx.x;

    if (tid == 0) d_bar = 0;

    for (size_t i = tid; i < (size_t)NG * EMB; i += stride) {
        int R = (int)(i >> 9), k = (int)(i & 511);
        int cta = R >> 5, g = (R >> 3) & 3, jj = R & 7;
        int j = cta * 8 + jj;
        const float* w = (g == 0) ? W_ii : (g == 1) ? W_if : (g == 2) ? W_ig : W_io;
        float v = w[j * EMB + k];
        __nv_bfloat16 hi = __float2bfloat16_rn(v);
        d_wxb[i] = hi;
        d_wxb[(size_t)NG * EMB + i] = __float2bfloat16_rn(v - __bfloat162float(hi));
    }
    for (size_t i = tid; i < NG; i += stride) {
        int R = (int)i;
        int cta = R >> 5, g = (R >> 3) & 3, jj = R & 7;
        int j = cta * 8 + jj;
        const float* b = (g == 0) ? b_ii : (g == 1) ? b_if : (g == 2) ? b_ig : b_io;
        d_bxr[R] = b[j];
    }
    for (size_t i = tid; i < (size_t)2 * NG * HID; i += stride) {
        int Re = (int)(i >> 10), k = (int)(i & 1023);
        int cta = Re >> 6, rem = Re & 63;
        int split = rem >> 5, local = rem & 31;
        int g = local >> 3, jj = local & 7;
        int j = cta * 8 + jj;
        const float* w = (g == 0) ? W_hi : (g == 1) ? W_hf : (g == 2) ? W_hg : W_ho;
        float v = w[j * HID + k];
        __half hi = __float2half_rn(v);
        if (split == 0) d_whf[i] = hi;
        else            d_whf[i] = __float2half_rn(v - __half2float(hi));
    }
    for (size_t i = tid; i < BB * HID; i += stride) {
        d_hf16[0][i] = __float2half_rn(0.0f);
        d_hf16[1][i] = __float2half_rn(0.0f);
    }
}

// =====================================================================
// gather (unchanged)
// =====================================================================
__global__ void gather_kernel(const int* __restrict__ x, const float* __restrict__ emb)
{
    ull* ehi = (ull*)d_ebf;
    ull* elo = (ull*)(d_ebf + (size_t)NM * EMB);
    const size_t stride = (size_t)gridDim.x * blockDim.x;
    for (size_t idx = (size_t)blockIdx.x * blockDim.x + threadIdx.x;
         idx < (size_t)NM * 128; idx += stride) {
        int m = (int)(idx >> 7), q = (int)(idx & 127);
        int s = m >> 6, b = m & 63;
        int tok = __ldg(&x[b * SEQ + s]);
        float4 v = *(const float4*)(emb + (size_t)tok * EMB + q * 4);
        float la, lb, lc, ld;
        ull hv = pack4bf(v.x, v.y, v.z, v.w, la, lb, lc, ld);
        float dum0, dum1, dum2, dum3;
        ull lv = pack4bf(la, lb, lc, ld, dum0, dum1, dum2, dum3);
        ehi[(size_t)m * 128 + q] = hv;
        elo[(size_t)m * 128 + q] = lv;
    }
}

// =====================================================================
// gx2 (unchanged from 6666us baseline)
// =====================================================================
#define G2_PITCH 144
#define G2_SPL   18432
#define G2_BUFSZ 36864
#define G2_OFF_B 73728
#define G2_SMEM  147456

__global__ void __launch_bounds__(256, 1) gx2_kernel()
{
    extern __shared__ char smc[];
    const unsigned smb = smem_u32(smc);
    const int t = threadIdx.x, w = t >> 5, lane = t & 31;
    const int mty = blockIdx.x;
    const int ntx = blockIdx.y;
    const int wm = w >> 1, wn = w & 1;
    const int lrow = lane & 15;
    const int kh2 = (lane >> 4) * 16;

    const __nv_bfloat16* wsrc = d_wxb;
    const __nv_bfloat16* esrc = d_ebf;

    float d[2][4][2][4];
#pragma unroll
    for (int mt = 0; mt < 2; mt++)
#pragma unroll
        for (int bt = 0; bt < 4; bt++)
#pragma unroll
            for (int hf = 0; hf < 2; hf++)
#pragma unroll
                for (int q = 0; q < 4; q++) d[mt][bt][hf][q] = 0.0f;

    auto stage = [&](int cb) {
        const int buf = cb & 1;
        char* abase = smc + buf * G2_BUFSZ;
        char* bbase = smc + G2_OFF_B + buf * G2_BUFSZ;
#pragma unroll
        for (int i = 0; i < 8; i++) {
            int u = t + i * 256;
            int split = u >> 10, r = (u >> 3) & 127, q = u & 7;
            cp16(abase + split * G2_SPL + r * G2_PITCH + q * 16,
                 wsrc + (size_t)split * NG * EMB + (size_t)(mty * 128 + r) * EMB + cb * 64 + q * 8);
        }
#pragma unroll
        for (int i = 0; i < 8; i++) {
            int u = t + i * 256;
            int split = u >> 10, r = (u >> 3) & 127, q = u & 7;
            cp16(bbase + split * G2_SPL + r * G2_PITCH + q * 16,
                 esrc + (size_t)split * NM * EMB + (size_t)(ntx * 128 + r) * EMB + cb * 64 + q * 8);
        }
        cp_commit();
    };

    stage(0);

    for (int cb = 0; cb < 8; cb++) {
        if (cb < 7) { stage(cb + 1); cp_wait<1>(); }
        else        { cp_wait<0>(); }
        __syncthreads();

        const unsigned abase = smb + (cb & 1) * G2_BUFSZ;
        const unsigned bbase = smb + G2_OFF_B + (cb & 1) * G2_BUFSZ;
#pragma unroll
        for (int k16 = 0; k16 < 4; k16++) {
            const int kB = k16 * 32 + kh2;
            unsigned Ah[2][4], Al[2][4];
#pragma unroll
            for (int mt = 0; mt < 2; mt++) {
                unsigned ar = abase + (wm * 32 + mt * 16 + lrow) * G2_PITCH + kB;
                ldm_x4(Ah[mt][0], Ah[mt][1], Ah[mt][2], Ah[mt][3], ar);
                ldm_x4(Al[mt][0], Al[mt][1], Al[mt][2], Al[mt][3], ar + G2_SPL);
            }
#pragma unroll
            for (int bt = 0; bt < 4; bt++) {
                unsigned br = bbase + (wn * 64 + bt * 16 + lrow) * G2_PITCH + kB;
                unsigned bh0, bh1, bh2, bh3, bl0, bl1, bl2, bl3;
                ldm_x4(bh0, bh1, bh2, bh3, br);
                ldm_x4(bl0, bl1, bl2, bl3, br + G2_SPL);
#pragma unroll
                for (int mt = 0; mt < 2; mt++) {
                    mma16816bf(d[mt][bt][0], Ah[mt], bh0, bh2);
                    mma16816bf(d[mt][bt][1], Ah[mt], bh1, bh3);
                    mma16816bf(d[mt][bt][0], Al[mt], bh0, bh2);
                    mma16816bf(d[mt][bt][1], Al[mt], bh1, bh3);
                    mma16816bf(d[mt][bt][0], Ah[mt], bl0, bl2);
                    mma16816bf(d[mt][bt][1], Ah[mt], bl1, bl3);
                }
            }
        }
        __syncthreads();
    }

#pragma unroll
    for (int mt = 0; mt < 2; mt++) {
        int Rg0 = mty * 128 + wm * 32 + mt * 16 + (lane >> 2);
        int Rg1 = Rg0 + 8;
        float bi0 = __ldg(&d_bxr[Rg0]);
        float bi1 = __ldg(&d_bxr[Rg1]);
#pragma unroll
        for (int bt = 0; bt < 4; bt++)
#pragma unroll
            for (int hf = 0; hf < 2; hf++) {
                int col = wn * 64 + bt * 16 + hf * 8 + 2 * (lane & 3);
                int m = ntx * 128 + col;
                int s = m >> 6, b = m & 63;
                float* q = d[mt][bt][hf];
                *(float2*)(&d_gx[((size_t)s * NG + Rg0) * BB + b]) =
                    make_float2(q[0] + bi0, q[1] + bi0);
                *(float2*)(&d_gx[((size_t)s * NG + Rg1) * BB + b]) =
                    make_float2(q[2] + bi1, q[3] + bi1);
            }
    }
}

// =====================================================================
// persistent mma.sync step kernel — 256 threads (8 warps, tile 16m x 16n).
// h single fp16 (ping-pong global), W fp16 hi/lo in SMEM once.
// Per k16: 3 ldm.x4 (W hi, W lo, h) + 4 mma. 4 chunks of k=256 -> 8 syncs.
// =====================================================================
#define W_PITCH 2064
#define H_PITCH 528
#define HBUF (64 * H_PITCH)            // 33792
#define OFF_W   0                      // 132096
#define OFF_H   132096                 // 2 x 33792 = 67584
#define OFF_SG  199680                 // 8704
#define OFF_SGX 208384                 // 8704
#define TC_SMEM 217088

__global__ void __launch_bounds__(256, 1) persist_mma_kernel()
{
    extern __shared__ char smc[];
    float* sg  = (float*)(smc + OFF_SG);
    float* sgx = (float*)(smc + OFF_SGX);

    const int t = threadIdx.x, w = t >> 5, lane = t & 31;
    const int cta = blockIdx.x;
    const int wm = w >> 2, wn = w & 3;
    const unsigned smb = smem_u32(smc);

    // ---- stage W slab once: 64 ext rows x 2048 B ----
    const char* wsrc = (const char*)(d_whf + (size_t)cta * 64 * HID);
#pragma unroll
    for (int i = 0; i < 32; i++) {
        int u = t + i * 256;
        int r = u >> 7, q = u & 127;
        cp16(smc + OFF_W + r * W_PITCH + q * 16, wsrc + r * 2048 + q * 16);
    }
    cp_commit();

    const int lrow = lane & 15;
    const int kh2 = (lane >> 4) * 16;

    const int be = t & 63, jp = t >> 6;
    float creg[2] = {0.0f, 0.0f};

    // prefetch gx for s = 0
#pragma unroll
    for (int i = 0; i < 2; i++) {
        int u = t + i * 256;
        int r = u >> 4, bq = (u & 15) * 4;
        cp16((char*)sgx + (r * 68 + bq) * 4,
             d_gx + ((size_t)0 * NG + cta * 32 + r) * BB + bq);
    }
    cp_commit();
    cp_wait<0>();
    __syncthreads();

    for (int s = 0; s < SEQ; s++) {
        const char* hsrc = (const char*)d_hf16[s & 1];
        __half* hdst = d_hf16[(s + 1) & 1];

        // ---- stage h chunk 0 (64 rows x 512 B) ----
#pragma unroll
        for (int i = 0; i < 8; i++) {
            int u = t + i * 256;
            int r = u >> 5, q = u & 31;
            cp16(smc + OFF_H + r * H_PITCH + q * 16, hsrc + r * 2048 + 0 + q * 16);
        }
        cp_commit();

        float d[2][4];
#pragma unroll
        for (int nt = 0; nt < 2; nt++)
#pragma unroll
            for (int q = 0; q < 4; q++) d[nt][q] = 0.0f;

        for (int kb = 0; kb < 4; kb++) {
            __syncthreads();   // consumers done with buf (kb+1)&1
            if (kb < 3) {
                char* nxt = smc + OFF_H + ((kb + 1) & 1) * HBUF;
#pragma unroll
                for (int i = 0; i < 8; i++) {
                    int u = t + i * 256;
                    int r = u >> 5, q = u & 31;
                    cp16(nxt + r * H_PITCH + q * 16, hsrc + r * 2048 + (kb + 1) * 512 + q * 16);
                }
                cp_commit();
                cp_wait<1>();
            } else {
                cp_wait<0>();
            }
            __syncthreads();   // chunk kb visible

            const unsigned aw  = smb + OFF_W + (wm * 16 + lrow) * W_PITCH + kb * 512;
            const unsigned awl = aw + 32 * W_PITCH;
            const unsigned hb  = smb + OFF_H + (kb & 1) * HBUF + (wn * 16 + lrow) * H_PITCH;
#pragma unroll
            for (int k16 = 0; k16 < 16; k16++) {
                const int kB = k16 * 32 + kh2;
                unsigned ah[4], al[4];
                unsigned b0, b1, b2, b3;
                ldm_x4(ah[0], ah[1], ah[2], ah[3], aw + kB);
                ldm_x4(al[0], al[1], al[2], al[3], awl + kB);
                ldm_x4(b0, b1, b2, b3, hb + kB);
                mma16816f16(d[0], ah, b0, b2);
                mma16816f16(d[1], ah, b1, b3);
                mma16816f16(d[0], al, b0, b2);
                mma16816f16(d[1], al, b1, b3);
            }
        }
        __syncthreads();

        // ---- write D tiles into sg[row][b] ----
#pragma unroll
        for (int nt = 0; nt < 2; nt++) {
            int col = wn * 16 + nt * 8 + (lane & 3) * 2;
            int row = wm * 16 + (lane >> 2);
            sg[row * 68 + col]           = d[nt][0];
            sg[row * 68 + col + 1]       = d[nt][1];
            sg[(row + 8) * 68 + col]     = d[nt][2];
            sg[(row + 8) * 68 + col + 1] = d[nt][3];
        }
        __syncthreads();

        // ---- pointwise: thread = (be, jj = 2jp, 2jp+1) ----
        unsigned short hph[2];
        float hf[2];
#pragma unroll
        for (int i = 0; i < 2; i++) {
            int jj = 2 * jp + i;
            float g[4];
#pragma unroll
            for (int gg = 0; gg < 4; gg++) {
                int r = gg * 8 + jj;
                g[gg] = sg[r * 68 + be] + sgx[r * 68 + be];
            }
            float it_ = sigf(g[0]);
            float ft  = sigf(g[1]);
            float gt  = tanhf(g[2]);
            float ot  = sigf(g[3]);
            float c = ft * creg[i] + it_ * gt;
            creg[i] = c;
            float h = ot * tanhf(c);
            hf[i] = h;
            __half hh = __float2half_rn(h);
            hph[i] = *(unsigned short*)&hh;
        }
        const int jglob = cta * 8 + 2 * jp;
        *(unsigned*)(&hdst[be * HID + jglob]) = *(unsigned*)hph;
        if (s == SEQ - 1)
            *(float2*)(&d_hfin[be * HID + jglob]) = make_float2(hf[0], hf[1]);

        // ---- barrier: arrive, prefetch gx(s+1) in the window, poll ----
        __threadfence();
        __syncthreads();
        if (t == 0) atomicAdd(&d_bar, 1);
        if (s + 1 < SEQ) {
#pragma unroll
            for (int i = 0; i < 2; i++) {
                int u = t + i * 256;
                int r = u >> 4, bq = (u & 15) * 4;
                cp16((char*)sgx + (r * 68 + bq) * 4,
                     d_gx + ((size_t)(s + 1) * NG + cta * 32 + r) * BB + bq);
            }
            cp_commit();
        }
        if (t == 0) {
            const int target = 128 * (s + 1);
            while (*(volatile int*)&d_bar < target) { }
        }
        __syncthreads();
    }

    const int jglob = cta * 8 + 2 * jp;
    *(float2*)(&d_cst[be * HID + jglob]) = make_float2(creg[0], creg[1]);
}

// =====================================================================
// head
// =====================================================================
__global__ void head_kernel(const float* __restrict__ Vw, const float* __restrict__ Vb,
                            float* __restrict__ out)
{
    const int b = blockIdx.x, t = threadIdx.x;
    float s0 = 0.0f, s1 = 0.0f;
    for (int k = t; k < HID; k += 256) {
        float hv = d_hfin[b * HID + k];
        s0 += hv * Vw[k];
        s1 += hv * Vw[HID + k];
        out[128 + b * HID + k] = hv;
        out[128 + BB * HID + b * HID + k] = d_cst[b * HID + k];
    }
    __shared__ float r0[256], r1[256];
    r0[t] = s0; r1[t] = s1;
    __syncthreads();
    for (int off = 128; off > 0; off >>= 1) {
        if (t < off) { r0[t] += r0[t + off]; r1[t] += r1[t + off]; }
        __syncthreads();
    }
    if (t == 0) {
        out[b * 2 + 0] = r0[0] + Vb[0];
        out[b * 2 + 1] = r1[0] + Vb[1];
    }
}

// =====================================================================
extern "C" void kernel_launch(void* const* d_in, const int* in_sizes, int n_in,
                              void* d_out, int out_size)
{
    (void)in_sizes; (void)n_in; (void)out_size;
    const int*   x   = (const int*)d_in[0];
    const float* emb = (const float*)d_in[1];

    cudaFuncSetAttribute(gx2_kernel,         cudaFuncAttributeMaxDynamicSharedMemorySize, G2_SMEM);
    cudaFuncSetAttribute(persist_mma_kernel, cudaFuncAttributeMaxDynamicSharedMemorySize, TC_SMEM);

    prepack_kernel<<<1024, 256>>>(
        (const float*)d_in[2],  (const float*)d_in[3],  (const float*)d_in[4],
        (const float*)d_in[5],  (const float*)d_in[6],  (const float*)d_in[7],
        (const float*)d_in[8],  (const float*)d_in[9],  (const float*)d_in[10],
        (const float*)d_in[11], (const float*)d_in[12], (const float*)d_in[13]);

    gather_kernel<<<2048, 256>>>(x, emb);

    gx2_kernel<<<dim3(32, 256), 256, G2_SMEM>>>();

    persist_mma_kernel<<<128, 256, TC_SMEM>>>();

    head_kernel<<<BB, 256>>>((const float*)d_in[14], (const float*)d_in[15], (float*)d_out);
}

// round 13
// speedup vs baseline: 1.6072x; 1.0708x over previous
#include <cuda_runtime.h>
#include <cuda_bf16.h>
#include <cuda_fp16.h>
#include <math.h>

#define SEQ 512
#define BB  64
#define EMB 512
#define HID 1024
#define NG  4096
#define NM  32768

typedef unsigned long long ull;

// ---------------- device scratch ----------------
__device__ float d_gx[(size_t)SEQ * NG * BB];                  // [s][R][b]
__device__ __align__(16) __half d_wxf[(size_t)2 * NG * EMB];   // Wx fp16 hi/lo, R-order
__device__ float d_bxr[NG];
__device__ __align__(16) __half d_whf[(size_t)2 * NG * HID];   // Wh fp16 hi/lo, cta-slab order
__device__ __align__(16) __half d_ef16[(size_t)NM * EMB];      // gathered emb fp16 [m][k]
__device__ __align__(16) __half d_hf16[2][BB * HID];           // h fp16, ping-pong
__device__ float d_hfin[BB * HID];
__device__ float d_cst[BB * HID];
__device__ int   d_bar;

// ---------------- helpers ----------------
__device__ __forceinline__ float sigf(float x) { return 1.0f / (1.0f + __expf(-x)); }

__device__ __forceinline__ void cp16(void* smem_dst, const void* gsrc) {
    unsigned d = (unsigned)__cvta_generic_to_shared(smem_dst);
    asm volatile("cp.async.cg.shared.global [%0], [%1], 16;" :: "r"(d), "l"(gsrc));
}
__device__ __forceinline__ void cp_commit() { asm volatile("cp.async.commit_group;"); }
template <int N> __device__ __forceinline__ void cp_wait() {
    asm volatile("cp.async.wait_group %0;" :: "n"(N));
}
__device__ __forceinline__ unsigned smem_u32(const void* p) {
    return (unsigned)__cvta_generic_to_shared(p);
}
__device__ __forceinline__ void ldm_x4(unsigned& r0, unsigned& r1, unsigned& r2, unsigned& r3,
                                       unsigned addr) {
    asm volatile("ldmatrix.sync.aligned.m8n8.x4.shared.b16 {%0,%1,%2,%3}, [%4];"
                 : "=r"(r0), "=r"(r1), "=r"(r2), "=r"(r3) : "r"(addr));
}
__device__ __forceinline__ void mma16816f16(float* d, const unsigned* a, unsigned b0, unsigned b1) {
    asm volatile(
        "mma.sync.aligned.m16n8k16.row.col.f32.f16.f16.f32 "
        "{%0,%1,%2,%3}, {%4,%5,%6,%7}, {%8,%9}, {%0,%1,%2,%3};"
        : "+f"(d[0]), "+f"(d[1]), "+f"(d[2]), "+f"(d[3])
        : "r"(a[0]), "r"(a[1]), "r"(a[2]), "r"(a[3]), "r"(b0), "r"(b1));
}

// =====================================================================
// prepack: Wx fp16 hi/lo R-order; Wh fp16 hi/lo cta-slab order; zero h.
// =====================================================================
__global__ void prepack_kernel(
    const float* __restrict__ W_ii, const float* __restrict__ b_ii, const float* __restrict__ W_hi,
    const float* __restrict__ W_if, const float* __restrict__ b_if, const float* __restrict__ W_hf,
    const float* __restrict__ W_ig, const float* __restrict__ b_ig, const float* __restrict__ W_hg,
    const float* __restrict__ W_io, const float* __restrict__ b_io, const float* __restrict__ W_ho)
{
    const size_t stride = (size_t)gridDim.x * blockDim.x;
    const size_t tid = (size_t)blockIdx.x * blockDim.x + threadIdx.x;

    if (tid == 0) d_bar = 0;

    for (size_t i = tid; i < (size_t)NG * EMB; i += stride) {
        int R = (int)(i >> 9), k = (int)(i & 511);
        int cta = R >> 5, g = (R >> 3) & 3, jj = R & 7;
        int j = cta * 8 + jj;
        const float* w = (g == 0) ? W_ii : (g == 1) ? W_if : (g == 2) ? W_ig : W_io;
        float v = w[j * EMB + k];
        __half hi = __float2half_rn(v);
        d_wxf[i] = hi;
        d_wxf[(size_t)NG * EMB + i] = __float2half_rn(v - __half2float(hi));
    }
    for (size_t i = tid; i < NG; i += stride) {
        int R = (int)i;
        int cta = R >> 5, g = (R >> 3) & 3, jj = R & 7;
        int j = cta * 8 + jj;
        const float* b = (g == 0) ? b_ii : (g == 1) ? b_if : (g == 2) ? b_ig : b_io;
        d_bxr[R] = b[j];
    }
    for (size_t i = tid; i < (size_t)2 * NG * HID; i += stride) {
        int Re = (int)(i >> 10), k = (int)(i & 1023);
        int cta = Re >> 6, rem = Re & 63;
        int split = rem >> 5, local = rem & 31;
        int g = local >> 3, jj = local & 7;
        int j = cta * 8 + jj;
        const float* w = (g == 0) ? W_hi : (g == 1) ? W_hf : (g == 2) ? W_hg : W_ho;
        float v = w[j * HID + k];
        __half hi = __float2half_rn(v);
        if (split == 0) d_whf[i] = hi;
        else            d_whf[i] = __float2half_rn(v - __half2float(hi));
    }
    for (size_t i = tid; i < BB * HID; i += stride) {
        d_hf16[0][i] = __float2half_rn(0.0f);
        d_hf16[1][i] = __float2half_rn(0.0f);
    }
}

// =====================================================================
// gather: e rows m = s*64+b -> single fp16 [m][k].
// =====================================================================
__global__ void gather_kernel(const int* __restrict__ x, const float* __restrict__ emb)
{
    ull* eh = (ull*)d_ef16;
    const size_t stride = (size_t)gridDim.x * blockDim.x;
    for (size_t idx = (size_t)blockIdx.x * blockDim.x + threadIdx.x;
         idx < (size_t)NM * 128; idx += stride) {
        int m = (int)(idx >> 7), q = (int)(idx & 127);
        int s = m >> 6, b = m & 63;
        int tok = __ldg(&x[b * SEQ + s]);
        float4 v = *(const float4*)(emb + (size_t)tok * EMB + q * 4);
        __half h0 = __float2half_rn(v.x), h1 = __float2half_rn(v.y);
        __half h2 = __float2half_rn(v.z), h3 = __float2half_rn(v.w);
        ull pk = (ull)*(unsigned short*)&h0 | ((ull)*(unsigned short*)&h1 << 16)
               | ((ull)*(unsigned short*)&h2 << 32) | ((ull)*(unsigned short*)&h3 << 48);
        eh[(size_t)m * 128 + q] = pk;
    }
}

// =====================================================================
// gx2: fp16 HMMA GEMM  d_gx[s][R][b] = Wx(2-term) x e(fp16) + bias.
// M=4096(R), N=32768(m), K=512. Grid (32 mtiles, 256 ntiles), 256 thr.
// CTA tile 128R x 128m; warps 4m x 2n; warp tile 32R x 64m.
// 64-k chunks, double-buffered cp.async. Per k16/bt: 1 B ldm, per mt:
// A hi+lo ldm + 4 mma.
// =====================================================================
#define G2_PITCH 144
#define G2_SPL   18432            // 128 rows * 144
#define G2_ABUF  36864            // 2 splits
#define G2_OFF_B 73728            // after 2 A buffers
#define G2_BBUF  18432
#define G2_SMEM  110592

__global__ void __launch_bounds__(256, 1) gx2_kernel()
{
    extern __shared__ char smc[];
    const unsigned smb = smem_u32(smc);
    const int t = threadIdx.x, w = t >> 5, lane = t & 31;
    const int mty = blockIdx.x;
    const int ntx = blockIdx.y;
    const int wm = w >> 1, wn = w & 1;
    const int lrow = lane & 15;
    const int kh2 = (lane >> 4) * 16;

    float d[2][4][2][4];
#pragma unroll
    for (int mt = 0; mt < 2; mt++)
#pragma unroll
        for (int bt = 0; bt < 4; bt++)
#pragma unroll
            for (int hf = 0; hf < 2; hf++)
#pragma unroll
                for (int q = 0; q < 4; q++) d[mt][bt][hf][q] = 0.0f;

    auto stage = [&](int cb) {
        const int buf = cb & 1;
        char* abase = smc + buf * G2_ABUF;
        char* bbase = smc + G2_OFF_B + buf * G2_BBUF;
        // A: 2 splits x 128 rows x 64 k fp16 (2048 cp16)
#pragma unroll
        for (int i = 0; i < 8; i++) {
            int u = t + i * 256;
            int split = u >> 10, r = (u >> 3) & 127, q = u & 7;
            cp16(abase + split * G2_SPL + r * G2_PITCH + q * 16,
                 d_wxf + (size_t)split * NG * EMB + (size_t)(mty * 128 + r) * EMB + cb * 64 + q * 8);
        }
        // B: 128 rows x 64 k fp16 (1024 cp16)
#pragma unroll
        for (int i = 0; i < 4; i++) {
            int u = t + i * 256;
            int r = u >> 3, q = u & 7;
            cp16(bbase + r * G2_PITCH + q * 16,
                 d_ef16 + (size_t)(ntx * 128 + r) * EMB + cb * 64 + q * 8);
        }
        cp_commit();
    };

    stage(0);

    for (int cb = 0; cb < 8; cb++) {
        if (cb < 7) { stage(cb + 1); cp_wait<1>(); }
        else        { cp_wait<0>(); }
        __syncthreads();

        const unsigned abase = smb + (cb & 1) * G2_ABUF;
        const unsigned bbase = smb + G2_OFF_B + (cb & 1) * G2_BBUF;
#pragma unroll
        for (int k16 = 0; k16 < 4; k16++) {
            const int kB = k16 * 32 + kh2;
            unsigned Ah[2][4], Al[2][4];
#pragma unroll
            for (int mt = 0; mt < 2; mt++) {
                unsigned ar = abase + (wm * 32 + mt * 16 + lrow) * G2_PITCH + kB;
                ldm_x4(Ah[mt][0], Ah[mt][1], Ah[mt][2], Ah[mt][3], ar);
                ldm_x4(Al[mt][0], Al[mt][1], Al[mt][2], Al[mt][3], ar + G2_SPL);
            }
#pragma unroll
            for (int bt = 0; bt < 4; bt++) {
                unsigned br = bbase + (wn * 64 + bt * 16 + lrow) * G2_PITCH + kB;
                unsigned b0, b1, b2, b3;
                ldm_x4(b0, b1, b2, b3, br);
#pragma unroll
                for (int mt = 0; mt < 2; mt++) {
                    mma16816f16(d[mt][bt][0], Ah[mt], b0, b2);
                    mma16816f16(d[mt][bt][1], Ah[mt], b1, b3);
                    mma16816f16(d[mt][bt][0], Al[mt], b0, b2);
                    mma16816f16(d[mt][bt][1], Al[mt], b1, b3);
                }
            }
        }
        __syncthreads();
    }

#pragma unroll
    for (int mt = 0; mt < 2; mt++) {
        int Rg0 = mty * 128 + wm * 32 + mt * 16 + (lane >> 2);
        int Rg1 = Rg0 + 8;
        float bi0 = __ldg(&d_bxr[Rg0]);
        float bi1 = __ldg(&d_bxr[Rg1]);
#pragma unroll
        for (int bt = 0; bt < 4; bt++)
#pragma unroll
            for (int hf = 0; hf < 2; hf++) {
                int col = wn * 64 + bt * 16 + hf * 8 + 2 * (lane & 3);
                int m = ntx * 128 + col;
                int s = m >> 6, b = m & 63;
                float* q = d[mt][bt][hf];
                *(float2*)(&d_gx[((size_t)s * NG + Rg0) * BB + b]) =
                    make_float2(q[0] + bi0, q[1] + bi0);
                *(float2*)(&d_gx[((size_t)s * NG + Rg1) * BB + b]) =
                    make_float2(q[2] + bi1, q[3] + bi1);
            }
    }
}

// =====================================================================
// persistent mma.sync step kernel — unchanged from 5313us round.
// =====================================================================
#define W_PITCH 2064
#define H_PITCH 528
#define HBUF (64 * H_PITCH)
#define OFF_W   0
#define OFF_H   132096
#define OFF_SG  199680
#define OFF_SGX 208384
#define TC_SMEM 217088

__global__ void __launch_bounds__(256, 1) persist_mma_kernel()
{
    extern __shared__ char smc[];
    float* sg  = (float*)(smc + OFF_SG);
    float* sgx = (float*)(smc + OFF_SGX);

    const int t = threadIdx.x, w = t >> 5, lane = t & 31;
    const int cta = blockIdx.x;
    const int wm = w >> 2, wn = w & 3;
    const unsigned smb = smem_u32(smc);

    const char* wsrc = (const char*)(d_whf + (size_t)cta * 64 * HID);
#pragma unroll
    for (int i = 0; i < 32; i++) {
        int u = t + i * 256;
        int r = u >> 7, q = u & 127;
        cp16(smc + OFF_W + r * W_PITCH + q * 16, wsrc + r * 2048 + q * 16);
    }
    cp_commit();

    const int lrow = lane & 15;
    const int kh2 = (lane >> 4) * 16;

    const int be = t & 63, jp = t >> 6;
    float creg[2] = {0.0f, 0.0f};

#pragma unroll
    for (int i = 0; i < 2; i++) {
        int u = t + i * 256;
        int r = u >> 4, bq = (u & 15) * 4;
        cp16((char*)sgx + (r * 68 + bq) * 4,
             d_gx + ((size_t)0 * NG + cta * 32 + r) * BB + bq);
    }
    cp_commit();
    cp_wait<0>();
    __syncthreads();

    for (int s = 0; s < SEQ; s++) {
        const char* hsrc = (const char*)d_hf16[s & 1];
        __half* hdst = d_hf16[(s + 1) & 1];

#pragma unroll
        for (int i = 0; i < 8; i++) {
            int u = t + i * 256;
            int r = u >> 5, q = u & 31;
            cp16(smc + OFF_H + r * H_PITCH + q * 16, hsrc + r * 2048 + 0 + q * 16);
        }
        cp_commit();

        float d[2][4];
#pragma unroll
        for (int nt = 0; nt < 2; nt++)
#pragma unroll
            for (int q = 0; q < 4; q++) d[nt][q] = 0.0f;

        for (int kb = 0; kb < 4; kb++) {
            __syncthreads();
            if (kb < 3) {
                char* nxt = smc + OFF_H + ((kb + 1) & 1) * HBUF;
#pragma unroll
                for (int i = 0; i < 8; i++) {
                    int u = t + i * 256;
                    int r = u >> 5, q = u & 31;
                    cp16(nxt + r * H_PITCH + q * 16, hsrc + r * 2048 + (kb + 1) * 512 + q * 16);
                }
                cp_commit();
                cp_wait<1>();
            } else {
                cp_wait<0>();
            }
            __syncthreads();

            const unsigned aw  = smb + OFF_W + (wm * 16 + lrow) * W_PITCH + kb * 512;
            const unsigned awl = aw + 32 * W_PITCH;
            const unsigned hb  = smb + OFF_H + (kb & 1) * HBUF + (wn * 16 + lrow) * H_PITCH;
#pragma unroll
            for (int k16 = 0; k16 < 16; k16++) {
                const int kB = k16 * 32 + kh2;
                unsigned ah[4], al[4];
                unsigned b0, b1, b2, b3;
                ldm_x4(ah[0], ah[1], ah[2], ah[3], aw + kB);
                ldm_x4(al[0], al[1], al[2], al[3], awl + kB);
                ldm_x4(b0, b1, b2, b3, hb + kB);
                mma16816f16(d[0], ah, b0, b2);
                mma16816f16(d[1], ah, b1, b3);
                mma16816f16(d[0], al, b0, b2);
                mma16816f16(d[1], al, b1, b3);
            }
        }
        __syncthreads();

#pragma unroll
        for (int nt = 0; nt < 2; nt++) {
            int col = wn * 16 + nt * 8 + (lane & 3) * 2;
            int row = wm * 16 + (lane >> 2);
            sg[row * 68 + col]           = d[nt][0];
            sg[row * 68 + col + 1]       = d[nt][1];
            sg[(row + 8) * 68 + col]     = d[nt][2];
            sg[(row + 8) * 68 + col + 1] = d[nt][3];
        }
        __syncthreads();

        unsigned short hph[2];
        float hf[2];
#pragma unroll
        for (int i = 0; i < 2; i++) {
            int jj = 2 * jp + i;
            float g[4];
#pragma unroll
            for (int gg = 0; gg < 4; gg++) {
                int r = gg * 8 + jj;
                g[gg] = sg[r * 68 + be] + sgx[r * 68 + be];
            }
            float it_ = sigf(g[0]);
            float ft  = sigf(g[1]);
            float gt  = tanhf(g[2]);
            float ot  = sigf(g[3]);
            float c = ft * creg[i] + it_ * gt;
            creg[i] = c;
            float h = ot * tanhf(c);
            hf[i] = h;
            __half hh = __float2half_rn(h);
            hph[i] = *(unsigned short*)&hh;
        }
        const int jglob = cta * 8 + 2 * jp;
        *(unsigned*)(&hdst[be * HID + jglob]) = *(unsigned*)hph;
        if (s == SEQ - 1)
            *(float2*)(&d_hfin[be * HID + jglob]) = make_float2(hf[0], hf[1]);

        __threadfence();
        __syncthreads();
        if (t == 0) atomicAdd(&d_bar, 1);
        if (s + 1 < SEQ) {
#pragma unroll
            for (int i = 0; i < 2; i++) {
                int u = t + i * 256;
                int r = u >> 4, bq = (u & 15) * 4;
                cp16((char*)sgx + (r * 68 + bq) * 4,
                     d_gx + ((size_t)(s + 1) * NG + cta * 32 + r) * BB + bq);
            }
            cp_commit();
        }
        if (t == 0) {
            const int target = 128 * (s + 1);
            while (*(volatile int*)&d_bar < target) { }
        }
        __syncthreads();
    }

    const int jglob = cta * 8 + 2 * jp;
    *(float2*)(&d_cst[be * HID + jglob]) = make_float2(creg[0], creg[1]);
}

// =====================================================================
// head
// =====================================================================
__global__ void head_kernel(const float* __restrict__ Vw, const float* __restrict__ Vb,
                            float* __restrict__ out)
{
    const int b = blockIdx.x, t = threadIdx.x;
    float s0 = 0.0f, s1 = 0.0f;
    for (int k = t; k < HID; k += 256) {
        float hv = d_hfin[b * HID + k];
        s0 += hv * Vw[k];
        s1 += hv * Vw[HID + k];
        out[128 + b * HID + k] = hv;
        out[128 + BB * HID + b * HID + k] = d_cst[b * HID + k];
    }
    __shared__ float r0[256], r1[256];
    r0[t] = s0; r1[t] = s1;
    __syncthreads();
    for (int off = 128; off > 0; off >>= 1) {
        if (t < off) { r0[t] += r0[t + off]; r1[t] += r1[t + off]; }
        __syncthreads();
    }
    if (t == 0) {
        out[b * 2 + 0] = r0[0] + Vb[0];
        out[b * 2 + 1] = r1[0] + Vb[1];
    }
}

// =====================================================================
extern "C" void kernel_launch(void* const* d_in, const int* in_sizes, int n_in,
                              void* d_out, int out_size)
{
    (void)in_sizes; (void)n_in; (void)out_size;
    const int*   x   = (const int*)d_in[0];
    const float* emb = (const float*)d_in[1];

    cudaFuncSetAttribute(gx2_kernel,         cudaFuncAttributeMaxDynamicSharedMemorySize, G2_SMEM);
    cudaFuncSetAttribute(persist_mma_kernel, cudaFuncAttributeMaxDynamicSharedMemorySize, TC_SMEM);

    prepack_kernel<<<1024, 256>>>(
        (const float*)d_in[2],  (const float*)d_in[3],  (const float*)d_in[4],
        (const float*)d_in[5],  (const float*)d_in[6],  (const float*)d_in[7],
        (const float*)d_in[8],  (const float*)d_in[9],  (const float*)d_in[10],
        (const float*)d_in[11], (const float*)d_in[12], (const float*)d_in[13]);

    gather_kernel<<<2048, 256>>>(x, emb);

    gx2_kernel<<<dim3(32, 256), 256, G2_SMEM>>>();

    persist_mma_kernel<<<128, 256, TC_SMEM>>>();

    head_kernel<<<BB, 256>>>((const float*)d_in[14], (const float*)d_in[15], (float*)d_out);
}

// round 14
// speedup vs baseline: 1.6795x; 1.0450x over previous
#include <cuda_runtime.h>
#include <cuda_bf16.h>
#include <cuda_fp16.h>
#include <math.h>

#define SEQ 512
#define BB  64
#define EMB 512
#define HID 1024
#define NG  4096
#define NM  32768

typedef unsigned long long ull;

// ---------------- device scratch ----------------
__device__ float d_gx[(size_t)SEQ * NG * BB];                  // [s][R][b]
__device__ __align__(16) __half d_wxf[(size_t)2 * NG * EMB];   // Wx fp16 hi/lo, R-order
__device__ float d_bxr[NG];
__device__ __align__(16) __half d_whf[(size_t)2 * NG * HID];   // Wh fp16 hi/lo, cta-slab order
__device__ __align__(16) __half d_ef16[(size_t)NM * EMB];      // gathered emb fp16 [m][k]
__device__ __align__(16) __half d_hf16[2][BB * HID];           // h fp16, ping-pong
__device__ float d_hfin[BB * HID];
__device__ float d_cst[BB * HID];
__device__ int   d_bar;

// ---------------- helpers ----------------
__device__ __forceinline__ float sigf(float x) { return 1.0f / (1.0f + __expf(-x)); }

__device__ __forceinline__ void cp16(void* smem_dst, const void* gsrc) {
    unsigned d = (unsigned)__cvta_generic_to_shared(smem_dst);
    asm volatile("cp.async.cg.shared.global [%0], [%1], 16;" :: "r"(d), "l"(gsrc));
}
__device__ __forceinline__ void cp_commit() { asm volatile("cp.async.commit_group;"); }
template <int N> __device__ __forceinline__ void cp_wait() {
    asm volatile("cp.async.wait_group %0;" :: "n"(N));
}
__device__ __forceinline__ unsigned smem_u32(const void* p) {
    return (unsigned)__cvta_generic_to_shared(p);
}
__device__ __forceinline__ void ldm_x4(unsigned& r0, unsigned& r1, unsigned& r2, unsigned& r3,
                                       unsigned addr) {
    asm volatile("ldmatrix.sync.aligned.m8n8.x4.shared.b16 {%0,%1,%2,%3}, [%4];"
                 : "=r"(r0), "=r"(r1), "=r"(r2), "=r"(r3) : "r"(addr));
}
__device__ __forceinline__ void mma16816f16(float* d, const unsigned* a, unsigned b0, unsigned b1) {
    asm volatile(
        "mma.sync.aligned.m16n8k16.row.col.f32.f16.f16.f32 "
        "{%0,%1,%2,%3}, {%4,%5,%6,%7}, {%8,%9}, {%0,%1,%2,%3};"
        : "+f"(d[0]), "+f"(d[1]), "+f"(d[2]), "+f"(d[3])
        : "r"(a[0]), "r"(a[1]), "r"(a[2]), "r"(a[3]), "r"(b0), "r"(b1));
}

// =====================================================================
// prepack: Wx fp16 hi/lo R-order; Wh fp16 hi/lo cta-slab order; zero h.
// =====================================================================
__global__ void prepack_kernel(
    const float* __restrict__ W_ii, const float* __restrict__ b_ii, const float* __restrict__ W_hi,
    const float* __restrict__ W_if, const float* __restrict__ b_if, const float* __restrict__ W_hf,
    const float* __restrict__ W_ig, const float* __restrict__ b_ig, const float* __restrict__ W_hg,
    const float* __restrict__ W_io, const float* __restrict__ b_io, const float* __restrict__ W_ho)
{
    const size_t stride = (size_t)gridDim.x * blockDim.x;
    const size_t tid = (size_t)blockIdx.x * blockDim.x + threadIdx.x;

    if (tid == 0) d_bar = 0;

    for (size_t i = tid; i < (size_t)NG * EMB; i += stride) {
        int R = (int)(i >> 9), k = (int)(i & 511);
        int cta = R >> 5, g = (R >> 3) & 3, jj = R & 7;
        int j = cta * 8 + jj;
        const float* w = (g == 0) ? W_ii : (g == 1) ? W_if : (g == 2) ? W_ig : W_io;
        float v = w[j * EMB + k];
        __half hi = __float2half_rn(v);
        d_wxf[i] = hi;
        d_wxf[(size_t)NG * EMB + i] = __float2half_rn(v - __half2float(hi));
    }
    for (size_t i = tid; i < NG; i += stride) {
        int R = (int)i;
        int cta = R >> 5, g = (R >> 3) & 3, jj = R & 7;
        int j = cta * 8 + jj;
        const float* b = (g == 0) ? b_ii : (g == 1) ? b_if : (g == 2) ? b_ig : b_io;
        d_bxr[R] = b[j];
    }
    for (size_t i = tid; i < (size_t)2 * NG * HID; i += stride) {
        int Re = (int)(i >> 10), k = (int)(i & 1023);
        int cta = Re >> 6, rem = Re & 63;
        int split = rem >> 5, local = rem & 31;
        int g = local >> 3, jj = local & 7;
        int j = cta * 8 + jj;
        const float* w = (g == 0) ? W_hi : (g == 1) ? W_hf : (g == 2) ? W_hg : W_ho;
        float v = w[j * HID + k];
        __half hi = __float2half_rn(v);
        if (split == 0) d_whf[i] = hi;
        else            d_whf[i] = __float2half_rn(v - __half2float(hi));
    }
    for (size_t i = tid; i < BB * HID; i += stride) {
        d_hf16[0][i] = __float2half_rn(0.0f);
        d_hf16[1][i] = __float2half_rn(0.0f);
    }
}

// =====================================================================
// gather: e rows m = s*64+b -> single fp16 [m][k].
// =====================================================================
__global__ void gather_kernel(const int* __restrict__ x, const float* __restrict__ emb)
{
    ull* eh = (ull*)d_ef16;
    const size_t stride = (size_t)gridDim.x * blockDim.x;
    for (size_t idx = (size_t)blockIdx.x * blockDim.x + threadIdx.x;
         idx < (size_t)NM * 128; idx += stride) {
        int m = (int)(idx >> 7), q = (int)(idx & 127);
        int s = m >> 6, b = m & 63;
        int tok = __ldg(&x[b * SEQ + s]);
        float4 v = *(const float4*)(emb + (size_t)tok * EMB + q * 4);
        __half h0 = __float2half_rn(v.x), h1 = __float2half_rn(v.y);
        __half h2 = __float2half_rn(v.z), h3 = __float2half_rn(v.w);
        ull pk = (ull)*(unsigned short*)&h0 | ((ull)*(unsigned short*)&h1 << 16)
               | ((ull)*(unsigned short*)&h2 << 32) | ((ull)*(unsigned short*)&h3 << 48);
        eh[(size_t)m * 128 + q] = pk;
    }
}

// =====================================================================
// gx2: fp16 HMMA GEMM  d_gx[s][R][b] = Wx(2-term) x e(fp16) + bias.
// Now 2 CTAs/SM for latency hiding.
// =====================================================================
#define G2_PITCH 144
#define G2_SPL   18432
#define G2_ABUF  36864
#define G2_OFF_B 73728
#define G2_BBUF  18432
#define G2_SMEM  110592

__global__ void __launch_bounds__(256, 2) gx2_kernel()
{
    extern __shared__ char smc[];
    const unsigned smb = smem_u32(smc);
    const int t = threadIdx.x, w = t >> 5, lane = t & 31;
    const int mty = blockIdx.x;
    const int ntx = blockIdx.y;
    const int wm = w >> 1, wn = w & 1;
    const int lrow = lane & 15;
    const int kh2 = (lane >> 4) * 16;

    float d[2][4][2][4];
#pragma unroll
    for (int mt = 0; mt < 2; mt++)
#pragma unroll
        for (int bt = 0; bt < 4; bt++)
#pragma unroll
            for (int hf = 0; hf < 2; hf++)
#pragma unroll
                for (int q = 0; q < 4; q++) d[mt][bt][hf][q] = 0.0f;

    auto stage = [&](int cb) {
        const int buf = cb & 1;
        char* abase = smc + buf * G2_ABUF;
        char* bbase = smc + G2_OFF_B + buf * G2_BBUF;
#pragma unroll
        for (int i = 0; i < 8; i++) {
            int u = t + i * 256;
            int split = u >> 10, r = (u >> 3) & 127, q = u & 7;
            cp16(abase + split * G2_SPL + r * G2_PITCH + q * 16,
                 d_wxf + (size_t)split * NG * EMB + (size_t)(mty * 128 + r) * EMB + cb * 64 + q * 8);
        }
#pragma unroll
        for (int i = 0; i < 4; i++) {
            int u = t + i * 256;
            int r = u >> 3, q = u & 7;
            cp16(bbase + r * G2_PITCH + q * 16,
                 d_ef16 + (size_t)(ntx * 128 + r) * EMB + cb * 64 + q * 8);
        }
        cp_commit();
    };

    stage(0);

    for (int cb = 0; cb < 8; cb++) {
        if (cb < 7) { stage(cb + 1); cp_wait<1>(); }
        else        { cp_wait<0>(); }
        __syncthreads();

        const unsigned abase = smb + (cb & 1) * G2_ABUF;
        const unsigned bbase = smb + G2_OFF_B + (cb & 1) * G2_BBUF;
#pragma unroll
        for (int k16 = 0; k16 < 4; k16++) {
            const int kB = k16 * 32 + kh2;
            unsigned Ah[2][4], Al[2][4];
#pragma unroll
            for (int mt = 0; mt < 2; mt++) {
                unsigned ar = abase + (wm * 32 + mt * 16 + lrow) * G2_PITCH + kB;
                ldm_x4(Ah[mt][0], Ah[mt][1], Ah[mt][2], Ah[mt][3], ar);
                ldm_x4(Al[mt][0], Al[mt][1], Al[mt][2], Al[mt][3], ar + G2_SPL);
            }
#pragma unroll
            for (int bt = 0; bt < 4; bt++) {
                unsigned br = bbase + (wn * 64 + bt * 16 + lrow) * G2_PITCH + kB;
                unsigned b0, b1, b2, b3;
                ldm_x4(b0, b1, b2, b3, br);
#pragma unroll
                for (int mt = 0; mt < 2; mt++) {
                    mma16816f16(d[mt][bt][0], Ah[mt], b0, b2);
                    mma16816f16(d[mt][bt][1], Ah[mt], b1, b3);
                    mma16816f16(d[mt][bt][0], Al[mt], b0, b2);
                    mma16816f16(d[mt][bt][1], Al[mt], b1, b3);
                }
            }
        }
        __syncthreads();
    }

#pragma unroll
    for (int mt = 0; mt < 2; mt++) {
        int Rg0 = mty * 128 + wm * 32 + mt * 16 + (lane >> 2);
        int Rg1 = Rg0 + 8;
        float bi0 = __ldg(&d_bxr[Rg0]);
        float bi1 = __ldg(&d_bxr[Rg1]);
#pragma unroll
        for (int bt = 0; bt < 4; bt++)
#pragma unroll
            for (int hf = 0; hf < 2; hf++) {
                int col = wn * 64 + bt * 16 + hf * 8 + 2 * (lane & 3);
                int m = ntx * 128 + col;
                int s = m >> 6, b = m & 63;
                float* q = d[mt][bt][hf];
                *(float2*)(&d_gx[((size_t)s * NG + Rg0) * BB + b]) =
                    make_float2(q[0] + bi0, q[1] + bi0);
                *(float2*)(&d_gx[((size_t)s * NG + Rg1) * BB + b]) =
                    make_float2(q[2] + bi1, q[3] + bi1);
            }
    }
}

// =====================================================================
// persistent mma.sync step kernel — single-sync-per-chunk pipeline.
// 256 threads (8 warps, warp tile 16m x 16n), h fp16 ping-pong global,
// W fp16 hi/lo in SMEM once. 4 chunks of k=256; per chunk:
// cp_wait<0>; sync; stage(kb+1); compute(kb).  (8 syncs/step total)
// =====================================================================
#define W_PITCH 2064
#define H_PITCH 528
#define HBUF (64 * H_PITCH)
#define OFF_W   0
#define OFF_H   132096
#define OFF_SG  199680
#define OFF_SGX 208384
#define TC_SMEM 217088

__global__ void __launch_bounds__(256, 1) persist_mma_kernel()
{
    extern __shared__ char smc[];
    float* sg  = (float*)(smc + OFF_SG);
    float* sgx = (float*)(smc + OFF_SGX);

    const int t = threadIdx.x, w = t >> 5, lane = t & 31;
    const int cta = blockIdx.x;
    const int wm = w >> 2, wn = w & 3;
    const unsigned smb = smem_u32(smc);

    const char* wsrc = (const char*)(d_whf + (size_t)cta * 64 * HID);
#pragma unroll
    for (int i = 0; i < 32; i++) {
        int u = t + i * 256;
        int r = u >> 7, q = u & 127;
        cp16(smc + OFF_W + r * W_PITCH + q * 16, wsrc + r * 2048 + q * 16);
    }
    cp_commit();

    const int lrow = lane & 15;
    const int kh2 = (lane >> 4) * 16;

    const int be = t & 63, jp = t >> 6;
    float creg[2] = {0.0f, 0.0f};

    // prefetch gx for s = 0
#pragma unroll
    for (int i = 0; i < 2; i++) {
        int u = t + i * 256;
        int r = u >> 4, bq = (u & 15) * 4;
        cp16((char*)sgx + (r * 68 + bq) * 4,
             d_gx + ((size_t)0 * NG + cta * 32 + r) * BB + bq);
    }
    cp_commit();
    cp_wait<0>();
    __syncthreads();

    for (int s = 0; s < SEQ; s++) {
        const char* hsrc = (const char*)d_hf16[s & 1];
        __half* hdst = d_hf16[(s + 1) & 1];

        auto stage_h = [&](int kb) {
            char* dst = smc + OFF_H + (kb & 1) * HBUF;
#pragma unroll
            for (int i = 0; i < 8; i++) {
                int u = t + i * 256;
                int r = u >> 5, q = u & 31;
                cp16(dst + r * H_PITCH + q * 16, hsrc + r * 2048 + kb * 512 + q * 16);
            }
            cp_commit();
        };

        stage_h(0);

        float d[2][4];
#pragma unroll
        for (int nt = 0; nt < 2; nt++)
#pragma unroll
            for (int q = 0; q < 4; q++) d[nt][q] = 0.0f;

        for (int kb = 0; kb < 4; kb++) {
            cp_wait<0>();          // chunk kb (and anything older) complete
            __syncthreads();       // visible to all; all done with buf (kb+1)&1
            if (kb < 3) stage_h(kb + 1);

            const unsigned aw  = smb + OFF_W + (wm * 16 + lrow) * W_PITCH + kb * 512;
            const unsigned awl = aw + 32 * W_PITCH;
            const unsigned hb  = smb + OFF_H + (kb & 1) * HBUF + (wn * 16 + lrow) * H_PITCH;
#pragma unroll
            for (int k16 = 0; k16 < 16; k16++) {
                const int kB = k16 * 32 + kh2;
                unsigned ah[4], al[4];
                unsigned b0, b1, b2, b3;
                ldm_x4(ah[0], ah[1], ah[2], ah[3], aw + kB);
                ldm_x4(al[0], al[1], al[2], al[3], awl + kB);
                ldm_x4(b0, b1, b2, b3, hb + kB);
                mma16816f16(d[0], ah, b0, b2);
                mma16816f16(d[1], ah, b1, b3);
                mma16816f16(d[0], al, b0, b2);
                mma16816f16(d[1], al, b1, b3);
            }
        }
        __syncthreads();           // all compute done before sg overwrite

#pragma unroll
        for (int nt = 0; nt < 2; nt++) {
            int col = wn * 16 + nt * 8 + (lane & 3) * 2;
            int row = wm * 16 + (lane >> 2);
            sg[row * 68 + col]           = d[nt][0];
            sg[row * 68 + col + 1]       = d[nt][1];
            sg[(row + 8) * 68 + col]     = d[nt][2];
            sg[(row + 8) * 68 + col + 1] = d[nt][3];
        }
        __syncthreads();

        unsigned short hph[2];
        float hf[2];
#pragma unroll
        for (int i = 0; i < 2; i++) {
            int jj = 2 * jp + i;
            float g[4];
#pragma unroll
            for (int gg = 0; gg < 4; gg++) {
                int r = gg * 8 + jj;
                g[gg] = sg[r * 68 + be] + sgx[r * 68 + be];
            }
            float it_ = sigf(g[0]);
            float ft  = sigf(g[1]);
            float gt  = tanhf(g[2]);
            float ot  = sigf(g[3]);
            float c = ft * creg[i] + it_ * gt;
            creg[i] = c;
            float h = ot * tanhf(c);
            hf[i] = h;
            __half hh = __float2half_rn(h);
            hph[i] = *(unsigned short*)&hh;
        }
        const int jglob = cta * 8 + 2 * jp;
        *(unsigned*)(&hdst[be * HID + jglob]) = *(unsigned*)hph;
        if (s == SEQ - 1)
            *(float2*)(&d_hfin[be * HID + jglob]) = make_float2(hf[0], hf[1]);

        // ---- barrier: arrive, prefetch gx(s+1) in the window, poll ----
        __threadfence();
        __syncthreads();
        if (t == 0) atomicAdd(&d_bar, 1);
        if (s + 1 < SEQ) {
#pragma unroll
            for (int i = 0; i < 2; i++) {
                int u = t + i * 256;
                int r = u >> 4, bq = (u & 15) * 4;
                cp16((char*)sgx + (r * 68 + bq) * 4,
                     d_gx + ((size_t)(s + 1) * NG + cta * 32 + r) * BB + bq);
            }
            cp_commit();
        }
        if (t == 0) {
            const int target = 128 * (s + 1);
            while (*(volatile int*)&d_bar < target) { }
        }
        __syncthreads();
    }

    const int jglob = cta * 8 + 2 * jp;
    *(float2*)(&d_cst[be * HID + jglob]) = make_float2(creg[0], creg[1]);
}

// =====================================================================
// head
// =====================================================================
__global__ void head_kernel(const float* __restrict__ Vw, const float* __restrict__ Vb,
                            float* __restrict__ out)
{
    const int b = blockIdx.x, t = threadIdx.x;
    float s0 = 0.0f, s1 = 0.0f;
    for (int k = t; k < HID; k += 256) {
        float hv = d_hfin[b * HID + k];
        s0 += hv * Vw[k];
        s1 += hv * Vw[HID + k];
        out[128 + b * HID + k] = hv;
        out[128 + BB * HID + b * HID + k] = d_cst[b * HID + k];
    }
    __shared__ float r0[256], r1[256];
    r0[t] = s0; r1[t] = s1;
    __syncthreads();
    for (int off = 128; off > 0; off >>= 1) {
        if (t < off) { r0[t] += r0[t + off]; r1[t] += r1[t + off]; }
        __syncthreads();
    }
    if (t == 0) {
        out[b * 2 + 0] = r0[0] + Vb[0];
        out[b * 2 + 1] = r1[0] + Vb[1];
    }
}

// =====================================================================
extern "C" void kernel_launch(void* const* d_in, const int* in_sizes, int n_in,
                              void* d_out, int out_size)
{
    (void)in_sizes; (void)n_in; (void)out_size;
    const int*   x   = (const int*)d_in[0];
    const float* emb = (const float*)d_in[1];

    cudaFuncSetAttribute(gx2_kernel,         cudaFuncAttributeMaxDynamicSharedMemorySize, G2_SMEM);
    cudaFuncSetAttribute(persist_mma_kernel, cudaFuncAttributeMaxDynamicSharedMemorySize, TC_SMEM);

    prepack_kernel<<<1024, 256>>>(
        (const float*)d_in[2],  (const float*)d_in[3],  (const float*)d_in[4],
        (const float*)d_in[5],  (const float*)d_in[6],  (const float*)d_in[7],
        (const float*)d_in[8],  (const float*)d_in[9],  (const float*)d_in[10],
        (const float*)d_in[11], (const float*)d_in[12], (const float*)d_in[13]);

    gather_kernel<<<2048, 256>>>(x, emb);

    gx2_kernel<<<dim3(32, 256), 256, G2_SMEM>>>();

    persist_mma_kernel<<<128, 256, TC_SMEM>>>();

    head_kernel<<<BB, 256>>>((const float*)d_in[14], (const float*)d_in[15], (float*)d_out);
}